// round 16
// baseline (speedup 1.0000x reference)
#include <cuda_runtime.h>

// DTW loss: B=16, C=8, T=512 -> 128 independent 512x512 DTW DPs.
// R16: 2 warps x 32 lanes x 8 cols/lane (was 4 warps x 4 cols). Superstep =
//   4 rows x 8 cols (32 cells); sigma = lane + 41*warp -> SIGMX=72, NSS=200
//   (vs 276: fill/drain slashed). One cross-warp handoff only; warp0 polls
//   a frozen BIG block. Groups of 4 ss, one combined sentinel check.
// Interleaved shfls (R13) + min-tree a-precompute (R15a): row chain =
//   FMNMX+FADD; shfl latency hidden behind remaining rows.
// Lag algebra (exact): lag = IWS-31 = 10; with shfl shift +1, iter t reads
//   slot t-9; first real slot 31 = producer's first valid publish; last 158
//   = its last; 12-slot BIG guard covers t<9; group margin 5 iters -> cold.
// BIG-fill: fill carries bit-exact BIG (1e30+c==1e30 fp32); drain values
//   stay >= 0 (x pad zeros) and are never consumed in-window.

#define TT    512
#define IWS   41
#define SIGMX (31 + IWS)           // 72
#define NSS   (TT / 4 + SIGMX)     // 200 supersteps
#define NG    (NSS / 4)            // 50 groups
#define GUARD 12                   // guard slots (>= lag 10)
#define REG   (GUARD + NSS)        // 212 float4 region
#define XS4   (SIGMX + TT / 4 + SIGMX + 1)   // 273 float4
#define BIGF  1e30f

__device__ float        g_partials[128];
__device__ unsigned int g_counter = 0;

// One DP row: 8 cells. a_ = precomputed min(left, diag) for col 0.
#define ROW8(xi_, a_, cO_) do {                                                \
    const float t0 = fabsf((xi_) - y0) + fminf((a_), up0);                     \
    float m;                                                                   \
    m = fminf(up1, up0); const float t1 = fabsf((xi_) - y1) + fminf(t0, m);    \
    m = fminf(up2, up1); const float t2 = fabsf((xi_) - y2) + fminf(t1, m);    \
    m = fminf(up3, up2); const float t3 = fabsf((xi_) - y3) + fminf(t2, m);    \
    m = fminf(up4, up3); const float t4 = fabsf((xi_) - y4) + fminf(t3, m);    \
    m = fminf(up5, up4); const float t5 = fabsf((xi_) - y5) + fminf(t4, m);    \
    m = fminf(up6, up5); const float t6 = fabsf((xi_) - y6) + fminf(t5, m);    \
    m = fminf(up7, up6); const float t7 = fabsf((xi_) - y7) + fminf(t6, m);    \
    up0 = t0; up1 = t1; up2 = t2; up3 = t3;                                    \
    up4 = t4; up5 = t5; up6 = t6; up7 = t7; cO_ = t7;                          \
} while (0)

// One superstep (4 rows x 8 cols). Consumes a0..a3; produces next-ss a's
// from interleaved shfls (lane0 <- hq_, next ss's cross-warp slot).
#define SSP(xq_, hq_, k_) do {                                                 \
    ROW8(xq_.x, a0, c0);                                                       \
    float n0 = __shfl_up_sync(0xffffffffu, c0, 1);                             \
    ROW8(xq_.y, a1, c1);                                                       \
    float n1 = __shfl_up_sync(0xffffffffu, c1, 1);                             \
    ROW8(xq_.z, a2, c2);                                                       \
    float n2 = __shfl_up_sync(0xffffffffu, c2, 1);                             \
    ROW8(xq_.w, a3, c3);                                                       \
    float n3 = __shfl_up_sync(0xffffffffu, c3, 1);                             \
    if (lane == 0) { n0 = hq_.x; n1 = hq_.y; n2 = hq_.z; n3 = hq_.w; }         \
    if (prod) qq[k_] = make_float4(c0, c1, c2, c3);                            \
    a0 = fminf(n0, lvprev); a1 = fminf(n1, n0);                                \
    a2 = fminf(n2, n1);     a3 = fminf(n3, n2);                                \
    lvprev = n3;                                                               \
} while (0)

// Cold path: volatile re-poll one slot until its .w leaves sentinel.
#define FIXSLOT(h_, k_) do {                                                   \
    volatile float* vp = (volatile float*)(pp + (k_));                         \
    float w = vp[3];                                                           \
    while (w < 0.0f) { w = vp[3]; }                                            \
    (h_).x = vp[0]; (h_).y = vp[1]; (h_).z = vp[2]; (h_).w = w;                \
} while (0)

__global__ __launch_bounds__(64, 1)
void dtw_fused_kernel(const float* __restrict__ inputs,
                      const float* __restrict__ targets,
                      float* __restrict__ out) {
    const int p    = blockIdx.x;
    const float* x = inputs + p * TT;
    const int tid  = threadIdx.x;          // 0..63
    const int lane = tid & 31;
    const int warp = tid >> 5;             // 0 or 1
    const int sig  = lane + IWS * warp;

    __shared__ float4 xsbuf[XS4];          // x rows (1 float4/ss), 0-padded
    __shared__ float4 handbuf[4 + REG];    // 4 frozen BIG + 1 region

    {   // init smem
        float* xf = (float*)xsbuf;
        const int PRE = SIGMX * 4;                       // 288 floats
        for (int k = tid; k < PRE; k += 64) xf[k] = 0.0f;
        for (int k = PRE + TT + tid; k < XS4 * 4; k += 64) xf[k] = 0.0f;
        for (int k = tid; k < TT; k += 64) xf[PRE + k] = x[k];
        float* hf = (float*)handbuf;
        for (int k = tid; k < (4 + REG) * 4; k += 64) hf[k] = -1.0f;
    }
    __syncthreads();
    {   // guards -> BIG: warp0 block (4 float4) + region prefix (12 float4)
        float* hf = (float*)handbuf;
        for (int k = tid; k < (4 + GUARD) * 4; k += 64) hf[k] = BIGF;
    }

    // This lane's 8 column values of y (cols j = 8*tid+1 .. 8*tid+8).
    const float4 ya = ((const float4*)(targets + p * TT))[2 * tid];
    const float4 yb = ((const float4*)(targets + p * TT))[2 * tid + 1];
    const float y0 = ya.x, y1 = ya.y, y2 = ya.z, y3 = ya.w;
    const float y4 = yb.x, y5 = yb.y, y6 = yb.z, y7 = yb.w;

    float up0 = BIGF, up1 = BIGF, up2 = BIGF, up3 = BIGF;
    float up4 = BIGF, up5 = BIGF, up6 = BIGF, up7 = BIGF;
    float c0 = BIGF, c1 = BIGF, c2 = BIGF, c3 = BIGF;
    float a0 = (tid == 0) ? 0.0f : BIGF;   // dtw[0][0] for tid0 row 1
    float a1 = BIGF, a2 = BIGF, a3 = BIGF;
    float lvprev = BIGF;

    const bool prod = (lane == 31 && warp == 0);
    // consumer (warp1): iter t reads slot t-9 -> handbuf[16 + t - 9] =
    // handbuf[7 + t]; start pp = handbuf+7, advance 4/group. warp0: frozen
    // BIG block, pinc = 0.
    float4* pp = (warp == 1) ? (handbuf + 7) : handbuf;
    const int pinc = (warp == 1) ? 4 : 0;
    float4* qq = handbuf + 4 + GUARD;       // producer slot 0
    const float4* xp = xsbuf + SIGMX - sig;

    __syncthreads();

    for (int g = 0; g < NG; ++g) {
        float4 hq0 = pp[0], hq1 = pp[1], hq2 = pp[2], hq3 = pp[3];
        if ((hq0.w < 0.0f) | (hq1.w < 0.0f) | (hq2.w < 0.0f) | (hq3.w < 0.0f)) {
            FIXSLOT(hq0, 0); FIXSLOT(hq1, 1); FIXSLOT(hq2, 2); FIXSLOT(hq3, 3);
        }

        const float4 xq0 = xp[0], xq1 = xp[1], xq2 = xp[2], xq3 = xp[3];

        SSP(xq0, hq0, 0);
        SSP(xq1, hq1, 1);
        SSP(xq2, hq2, 2);
        SSP(xq3, hq3, 3);

        pp += pinc; qq += 4; xp += 4;
    }

    // tid 63 (sig = 72): last valid ss = 199 = NSS-1; c3 = dtw[512][512].
    if (tid == 63) {
        g_partials[p] = c3 * (1.0f / (float)TT);
        __threadfence();
        unsigned int old = atomicAdd(&g_counter, 1u);
        if (old == 127u) {
            volatile float* gp = g_partials;
            float sum = 0.0f;
            #pragma unroll 16
            for (int k = 0; k < 128; ++k) sum += gp[k];
            out[0] = sum * 0.125f;                       // (1/C) * sum_b
            *(volatile unsigned int*)&g_counter = 0;     // reset for replay
        }
    }
}

extern "C" void kernel_launch(void* const* d_in, const int* in_sizes, int n_in,
                              void* d_out, int out_size) {
    const float* inputs  = (const float*)d_in[0];
    const float* targets = (const float*)d_in[1];
    float* out = (float*)d_out;
    (void)in_sizes; (void)n_in; (void)out_size;

    dtw_fused_kernel<<<128, 64>>>(inputs, targets, out);
}